// round 6
// baseline (speedup 1.0000x reference)
#include <cuda_runtime.h>

#define L   24
#define VOL (L*L*L*L)          // 331776
#define NEVEN (VOL/2)          // 165888
#define NALL (4*VOL*9)         // 11943936 complex elements

#define NB_COMPUTE 1296        // NEVEN / 128
#define NB_COPY    4096
#define TPB        128

struct C33 { float2 a[9]; };

__device__ __forceinline__ float2 cfma(float2 p, float2 q, float2 acc){
    acc.x = fmaf(p.x, q.x, fmaf(-p.y, q.y, acc.x));
    acc.y = fmaf(p.x, q.y, fmaf( p.y, q.x, acc.y));
    return acc;
}
// acc += p * conj(q)
__device__ __forceinline__ float2 cfma_cj(float2 p, float2 q, float2 acc){
    acc.x = fmaf(p.x, q.x, fmaf( p.y, q.y, acc.x));
    acc.y = fmaf(-p.x, q.y, fmaf( p.y, q.x, acc.y));
    return acc;
}
// acc += conj(p) * q
__device__ __forceinline__ float2 cfma_cjA(float2 p, float2 q, float2 acc){
    acc.x = fmaf(p.x, q.x, fmaf( p.y, q.y, acc.x));
    acc.y = fmaf(p.x, q.y, fmaf(-p.y, q.x, acc.y));
    return acc;
}
__device__ __forceinline__ float2 cmul(float2 a, float2 b){
    return make_float2(a.x*b.x - a.y*b.y, a.x*b.y + a.y*b.x);
}

__device__ __forceinline__ void mzero(C33& M){
#pragma unroll
    for (int k = 0; k < 9; k++) M.a[k] = make_float2(0.f, 0.f);
}

__device__ __forceinline__ void loadM(C33& M, const float* __restrict__ re,
                                      const float* __restrict__ im, int idx){
    const float* pr = re + (long)idx * 9;
    const float* pi = im + (long)idx * 9;
#pragma unroll
    for (int k = 0; k < 9; k++) { M.a[k].x = __ldg(pr + k); M.a[k].y = __ldg(pi + k); }
}

// C = A @ B
__device__ __forceinline__ void mmul(C33& C, const C33& A, const C33& B){
#pragma unroll
    for (int r = 0; r < 3; r++)
#pragma unroll
        for (int c = 0; c < 3; c++) {
            float2 acc = make_float2(0.f, 0.f);
            acc = cfma(A.a[r*3+0], B.a[0*3+c], acc);
            acc = cfma(A.a[r*3+1], B.a[1*3+c], acc);
            acc = cfma(A.a[r*3+2], B.a[2*3+c], acc);
            C.a[r*3+c] = acc;
        }
}
// C = A @ B^dag
__device__ __forceinline__ void mmul_ABdag(C33& C, const C33& A, const C33& B){
#pragma unroll
    for (int r = 0; r < 3; r++)
#pragma unroll
        for (int c = 0; c < 3; c++) {
            float2 acc = make_float2(0.f, 0.f);
            acc = cfma_cj(A.a[r*3+0], B.a[c*3+0], acc);
            acc = cfma_cj(A.a[r*3+1], B.a[c*3+1], acc);
            acc = cfma_cj(A.a[r*3+2], B.a[c*3+2], acc);
            C.a[r*3+c] = acc;
        }
}
// C = A^dag @ B
__device__ __forceinline__ void mmul_AdagB(C33& C, const C33& A, const C33& B){
#pragma unroll
    for (int r = 0; r < 3; r++)
#pragma unroll
        for (int c = 0; c < 3; c++) {
            float2 acc = make_float2(0.f, 0.f);
            acc = cfma_cjA(A.a[0*3+r], B.a[0*3+c], acc);
            acc = cfma_cjA(A.a[1*3+r], B.a[1*3+c], acc);
            acc = cfma_cjA(A.a[2*3+r], B.a[2*3+c], acc);
            C.a[r*3+c] = acc;
        }
}
// f += cr * (A @ B)
__device__ __forceinline__ void mmul_axpy(C33& f, float cr, const C33& A, const C33& B){
#pragma unroll
    for (int r = 0; r < 3; r++)
#pragma unroll
        for (int c = 0; c < 3; c++) {
            float2 acc = make_float2(0.f, 0.f);
            acc = cfma(A.a[r*3+0], B.a[0*3+c], acc);
            acc = cfma(A.a[r*3+1], B.a[1*3+c], acc);
            acc = cfma(A.a[r*3+2], B.a[2*3+c], acc);
            f.a[r*3+c].x = fmaf(cr, acc.x, f.a[r*3+c].x);
            f.a[r*3+c].y = fmaf(cr, acc.y, f.a[r*3+c].y);
        }
}

__device__ __forceinline__ int SITE(int t, int z, int y, int x){
    return ((t * L + z) * L + y) * L + x;
}

__device__ __forceinline__ void add_staples(
    C33& f, const float* __restrict__ re, const float* __restrict__ im,
    int nuOff, int s, int sp, int sm, int s_pt, int smpt, float cf, float cb)
{
    C33 A, B, Cm, T1;
    loadM(A,  re, im, nuOff + s);
    loadM(B,  re, im, sp);
    loadM(Cm, re, im, nuOff + s_pt);
    mmul_ABdag(T1, B, Cm);
    mmul_axpy(f, cf, A, T1);

    loadM(A,  re, im, nuOff + sm);
    loadM(B,  re, im, sm);
    loadM(Cm, re, im, nuOff + smpt);
    mmul_AdagB(T1, A, B);
    mmul_axpy(f, cb, T1, Cm);
}

__global__ void __launch_bounds__(TPB)
fused_kernel(const float* __restrict__ xre,
             const float* __restrict__ xim,
             const float* __restrict__ coeff,
             float2* __restrict__ out)
{
    if (blockIdx.x >= NB_COMPUTE) {
        // ---------------- COPY ROLE: interleave re/im -> out, skip even dir-0 sites
        int ci = (blockIdx.x - NB_COMPUTE) * TPB + threadIdx.x;
        const int stride = NB_COPY * TPB;
        for (int e = ci; e < NALL; e += stride) {
            int m = e / 9;                      // matrix index
            bool skip = false;
            if (m < VOL) {                      // dir 0 region: skip even sites
                int x  = m % L;
                int r1 = m / L;
                int y  = r1 % L;
                int r2 = r1 / L;
                int zz = r2 % L;
                int tt = r2 / L;
                skip = (((x + y + zz + tt) & 1) == 0);
            }
            if (!skip)
                out[e] = make_float2(__ldg(xre + e), __ldg(xim + e));
        }
        return;
    }

    // ---------------- COMPUTE ROLE: even dir-0 sites
    int tid = blockIdx.x * TPB + threadIdx.x;   // < NEVEN

    int j    = tid % (L/2);
    int line = tid / (L/2);
    int y = line % L;
    int tz = line / L;
    int z = tz % L;
    int t = tz / L;
    int x = 2 * j + ((t + z + y) & 1);          // (t+z+y+x) even

    const float CS = 0.6366197723675814f * 0.75f / 6.0f;
    float c0s = CS * atanf(__ldg(coeff + 0));
    float c1s = CS * atanf(__ldg(coeff + 1));
    float c2s = CS * atanf(__ldg(coeff + 2));
    float c3s = CS * atanf(__ldg(coeff + 3));
    float c4s = CS * atanf(__ldg(coeff + 4));
    float c5s = CS * atanf(__ldg(coeff + 5));

    int tp = (t + 1 == L) ? 0 : t + 1;
    int zp = (z + 1 == L) ? 0 : z + 1;  int zm = (z == 0) ? L - 1 : z - 1;
    int yp = (y + 1 == L) ? 0 : y + 1;  int ym = (y == 0) ? L - 1 : y - 1;
    int xp = (x + 1 == L) ? 0 : x + 1;  int xm = (x == 0) ? L - 1 : x - 1;

    int s    = SITE(t,  z,  y,  x);
    int s_pt = SITE(tp, z,  y,  x);

    C33 f; mzero(f);
    add_staples(f, xre, xim, 1*VOL, s, SITE(t, zp, y, x), SITE(t, zm, y, x),
                s_pt, SITE(tp, zm, y, x), c0s, c1s);
    add_staples(f, xre, xim, 2*VOL, s, SITE(t, z, yp, x), SITE(t, z, ym, x),
                s_pt, SITE(tp, z, ym, x), c2s, c3s);
    add_staples(f, xre, xim, 3*VOL, s, SITE(t, z, y, xp), SITE(t, z, y, xm),
                s_pt, SITE(tp, z, y, xm), c4s, c5s);

    C33 U; loadM(U, xre, xim, s);

    // M = f @ U^dag
    C33 M; mmul_ABdag(M, f, U);

    // Q = -i * (antiherm(M) - tr/3): hermitian traceless
    // antiherm: A[r][c] = 0.5*(M[r][c] - conj(M[c][r]))
    C33 Q;
#pragma unroll
    for (int r = 0; r < 3; r++)
#pragma unroll
        for (int c = 0; c < 3; c++) {
            float2 m1 = M.a[r*3+c];
            float2 m2 = M.a[c*3+r];
            float zx = 0.5f * (m1.x - m2.x);     // Z real
            float zy = 0.5f * (m1.y + m2.y);     // Z imag
            Q.a[r*3+c] = make_float2(zy, -zx);   // Q = -iZ
        }
    // subtract trace/3 of Z -> for Q: tr(Q)/3 subtraction on diag
    {
        float qtx = (Q.a[0].x + Q.a[4].x + Q.a[8].x) * (1.f/3.f);
        float qty = (Q.a[0].y + Q.a[4].y + Q.a[8].y) * (1.f/3.f);
        Q.a[0].x -= qtx; Q.a[0].y -= qty;
        Q.a[4].x -= qtx; Q.a[4].y -= qty;
        Q.a[8].x -= qtx; Q.a[8].y -= qty;
    }

    // Q2 = Q @ Q
    C33 Q2; mmul(Q2, Q, Q);

    // c1 = 0.5 * Re tr(Q2);  c0 = Re det(Q)
    float c1 = 0.5f * (Q2.a[0].x + Q2.a[4].x + Q2.a[8].x);
    float c0;
    {
        float2 m00 = cmul(Q.a[4], Q.a[8]);
        float2 m01 = cmul(Q.a[5], Q.a[7]);
        float2 m10 = cmul(Q.a[3], Q.a[8]);
        float2 m11 = cmul(Q.a[5], Q.a[6]);
        float2 m20 = cmul(Q.a[3], Q.a[7]);
        float2 m21 = cmul(Q.a[4], Q.a[6]);
        float2 d0 = make_float2(m00.x - m01.x, m00.y - m01.y);
        float2 d1 = make_float2(m10.x - m11.x, m10.y - m11.y);
        float2 d2 = make_float2(m20.x - m21.x, m20.y - m21.y);
        c0 = cmul(Q.a[0], d0).x - cmul(Q.a[1], d1).x + cmul(Q.a[2], d2).x;
    }

    float2 f0, f1, f2;
    if (c1 < 1e-9f) {
        // Q ~ 0: exp(iQ) ~ I + iQ - Q^2/2
        f0 = make_float2(1.f, 0.f);
        f1 = make_float2(0.f, 1.f);
        f2 = make_float2(-0.5f, 0.f);
    } else {
        bool neg = (c0 < 0.f);
        float c0a = fabsf(c0);
        float c13 = c1 * (1.f/3.f);
        float sq13 = sqrtf(c13);
        float c0max = 2.f * c13 * sq13;
        float ratio = fminf(c0a / c0max, 1.0f);
        float theta = acosf(ratio);
        float th3 = theta * (1.f/3.f);
        float u = sq13 * cosf(th3);
        float w = sqrtf(c1) * sinf(th3);
        float u2 = u * u, w2 = w * w;
        float cw = cosf(w);
        float xi0;
        if (w < 0.05f) {
            xi0 = 1.f - w2*(1.f/6.f)*(1.f - w2*(1.f/20.f)*(1.f - w2*(1.f/42.f)));
        } else {
            xi0 = sinf(w) / w;
        }
        float su, cu;
        __sincosf(u, &su, &cu);      // fast path ok? use precise:
        su = sinf(u); cu = cosf(u);
        float c2u = fmaf(2.f*cu, cu, -1.f);   // cos 2u
        float s2u = 2.f * su * cu;            // sin 2u

        float denom = 9.f*u2 - w2;
        float mag = 9.f*u2 + w2 + 1e-30f;
        if (fabsf(denom) < 1e-7f * mag)
            denom = copysignf(1e-7f * mag, denom == 0.f ? 1.f : denom);
        float rden = 1.f / denom;

        // h0
        float a0 = 8.f*u2*cw;
        float b0 = 2.f*u*(3.f*u2 + w2)*xi0;
        float h0r = (u2 - w2)*c2u + cu*a0 + su*b0;
        float h0i = (u2 - w2)*s2u + cu*b0 - su*a0;
        // h1
        float a1 = 2.f*u*cw;
        float b1 = -(3.f*u2 - w2)*xi0;
        float h1r = 2.f*u*c2u - (cu*a1 + su*b1);
        float h1i = 2.f*u*s2u - (cu*b1 - su*a1);
        // h2
        float a2 = cw;
        float b2 = 3.f*u*xi0;
        float h2r = c2u - (cu*a2 + su*b2);
        float h2i = s2u - (cu*b2 - su*a2);

        f0 = make_float2(h0r*rden, h0i*rden);
        f1 = make_float2(h1r*rden, h1i*rden);
        f2 = make_float2(h2r*rden, h2i*rden);
        if (neg) {             // f_j(-c0) = (-1)^j conj(f_j)
            f0.y = -f0.y;
            f1.x = -f1.x;
            f2.y = -f2.y;
        }
    }

    // E = f0 I + f1 Q + f2 Q2
    C33 E;
#pragma unroll
    for (int k = 0; k < 9; k++) {
        float2 e = cmul(f1, Q.a[k]);
        float2 g = cmul(f2, Q2.a[k]);
        E.a[k] = make_float2(e.x + g.x, e.y + g.y);
    }
    E.a[0].x += f0.x; E.a[0].y += f0.y;
    E.a[4].x += f0.x; E.a[4].y += f0.y;
    E.a[8].x += f0.x; E.a[8].y += f0.y;

    // y[mu] = E @ U
    C33 Y; mmul(Y, E, U);

    float2* o = out + (long)s * 9;
#pragma unroll
    for (int k = 0; k < 9; k++) o[k] = Y.a[k];
}

extern "C" void kernel_launch(void* const* d_in, const int* in_sizes, int n_in,
                              void* d_out, int out_size)
{
    const float* xre   = (const float*)d_in[0];
    const float* xim   = (const float*)d_in[1];
    const float* coeff = (const float*)d_in[2];

    fused_kernel<<<NB_COMPUTE + NB_COPY, TPB>>>(
        xre, xim, coeff, (float2*)d_out);
}

// round 9
// speedup vs baseline: 1.3906x; 1.3906x over previous
#include <cuda_runtime.h>

#define L   24
#define VOL (L*L*L*L)          // 331776
#define NEVEN (VOL/2)          // 165888
#define NDIR0 (VOL*9)          // 2985984 complex elems in dir-0
#define NALL (4*VOL*9)         // 11943936 complex elems total

#define NB_COMPUTE 1296        // NEVEN / 128
#define NB_COPY    2048
#define NB_TOTAL   (NB_COMPUTE + NB_COPY)
#define TPB        128

// float4 groups covering dirs 1..3 of re/im (complex index base VOL*9)
#define BASE4 (NDIR0/4)        // 746496
#define N4A   ((3*VOL*9)/4)    // 2239488

struct C33 { float2 a[9]; };

__device__ __forceinline__ float2 cfma(float2 p, float2 q, float2 acc){
    acc.x = fmaf(p.x, q.x, fmaf(-p.y, q.y, acc.x));
    acc.y = fmaf(p.x, q.y, fmaf( p.y, q.x, acc.y));
    return acc;
}
// acc += p * conj(q)
__device__ __forceinline__ float2 cfma_cj(float2 p, float2 q, float2 acc){
    acc.x = fmaf(p.x, q.x, fmaf( p.y, q.y, acc.x));
    acc.y = fmaf(-p.x, q.y, fmaf( p.y, q.x, acc.y));
    return acc;
}
// acc += conj(p) * q
__device__ __forceinline__ float2 cfma_cjA(float2 p, float2 q, float2 acc){
    acc.x = fmaf(p.x, q.x, fmaf( p.y, q.y, acc.x));
    acc.y = fmaf(p.x, q.y, fmaf(-p.y, q.x, acc.y));
    return acc;
}
__device__ __forceinline__ float2 cmul(float2 a, float2 b){
    return make_float2(a.x*b.x - a.y*b.y, a.x*b.y + a.y*b.x);
}

__device__ __forceinline__ void mzero(C33& M){
#pragma unroll
    for (int k = 0; k < 9; k++) M.a[k] = make_float2(0.f, 0.f);
}

__device__ __forceinline__ void loadM(C33& M, const float* __restrict__ re,
                                      const float* __restrict__ im, int idx){
    const float* pr = re + (long)idx * 9;
    const float* pi = im + (long)idx * 9;
#pragma unroll
    for (int k = 0; k < 9; k++) { M.a[k].x = __ldg(pr + k); M.a[k].y = __ldg(pi + k); }
}

// C = A @ B
__device__ __forceinline__ void mmul(C33& C, const C33& A, const C33& B){
#pragma unroll
    for (int r = 0; r < 3; r++)
#pragma unroll
        for (int c = 0; c < 3; c++) {
            float2 acc = make_float2(0.f, 0.f);
            acc = cfma(A.a[r*3+0], B.a[0*3+c], acc);
            acc = cfma(A.a[r*3+1], B.a[1*3+c], acc);
            acc = cfma(A.a[r*3+2], B.a[2*3+c], acc);
            C.a[r*3+c] = acc;
        }
}
// C = A @ B^dag
__device__ __forceinline__ void mmul_ABdag(C33& C, const C33& A, const C33& B){
#pragma unroll
    for (int r = 0; r < 3; r++)
#pragma unroll
        for (int c = 0; c < 3; c++) {
            float2 acc = make_float2(0.f, 0.f);
            acc = cfma_cj(A.a[r*3+0], B.a[c*3+0], acc);
            acc = cfma_cj(A.a[r*3+1], B.a[c*3+1], acc);
            acc = cfma_cj(A.a[r*3+2], B.a[c*3+2], acc);
            C.a[r*3+c] = acc;
        }
}
// C = A^dag @ B
__device__ __forceinline__ void mmul_AdagB(C33& C, const C33& A, const C33& B){
#pragma unroll
    for (int r = 0; r < 3; r++)
#pragma unroll
        for (int c = 0; c < 3; c++) {
            float2 acc = make_float2(0.f, 0.f);
            acc = cfma_cjA(A.a[0*3+r], B.a[0*3+c], acc);
            acc = cfma_cjA(A.a[1*3+r], B.a[1*3+c], acc);
            acc = cfma_cjA(A.a[2*3+r], B.a[2*3+c], acc);
            C.a[r*3+c] = acc;
        }
}
// f += cr * (A @ B)
__device__ __forceinline__ void mmul_axpy(C33& f, float cr, const C33& A, const C33& B){
#pragma unroll
    for (int r = 0; r < 3; r++)
#pragma unroll
        for (int c = 0; c < 3; c++) {
            float2 acc = make_float2(0.f, 0.f);
            acc = cfma(A.a[r*3+0], B.a[0*3+c], acc);
            acc = cfma(A.a[r*3+1], B.a[1*3+c], acc);
            acc = cfma(A.a[r*3+2], B.a[2*3+c], acc);
            f.a[r*3+c].x = fmaf(cr, acc.x, f.a[r*3+c].x);
            f.a[r*3+c].y = fmaf(cr, acc.y, f.a[r*3+c].y);
        }
}

__device__ __forceinline__ int SITE(int t, int z, int y, int x){
    return ((t * L + z) * L + y) * L + x;
}

__device__ __forceinline__ void add_staples(
    C33& f, const float* __restrict__ re, const float* __restrict__ im,
    int nuOff, int s, int sp, int sm, int s_pt, int smpt, float cf, float cb)
{
    C33 A, B, Cm, T1;
    loadM(A,  re, im, nuOff + s);
    loadM(B,  re, im, sp);
    loadM(Cm, re, im, nuOff + s_pt);
    mmul_ABdag(T1, B, Cm);
    mmul_axpy(f, cf, A, T1);

    loadM(A,  re, im, nuOff + sm);
    loadM(B,  re, im, sm);
    loadM(Cm, re, im, nuOff + smpt);
    mmul_AdagB(T1, A, B);
    mmul_axpy(f, cb, T1, Cm);
}

__global__ void __launch_bounds__(TPB)
fused_kernel(const float* __restrict__ xre,
             const float* __restrict__ xim,
             const float* __restrict__ coeff,
             float2* __restrict__ out)
{
    // ---- role assignment: interleave compute/copy over the first 2*NB_COMPUTE
    // block indices so every wave co-resides both kinds on each SM.
    int bid = blockIdx.x;
    bool is_compute;
    int rid;                                   // role-local block id
    if (bid < 2 * NB_COMPUTE) {
        is_compute = ((bid & 1) == 0);
        rid = bid >> 1;
    } else {
        is_compute = false;
        rid = bid - NB_COMPUTE;                // continues copy ids after 1295
    }

    if (!is_compute) {
        int ci = rid * TPB + threadIdx.x;
        const int stride = NB_COPY * TPB;

        // ---- Loop A: dirs 1..3, pure float4 interleave (no checks) ----
        const float4* re4 = (const float4*)xre;
        const float4* im4 = (const float4*)xim;
        float4* out4 = (float4*)out;
        for (int i = ci; i < N4A; i += stride) {
            int gi = BASE4 + i;
            float4 r = __ldg(re4 + gi);
            float4 m = __ldg(im4 + gi);
            out4[2*gi + 0] = make_float4(r.x, m.x, r.y, m.y);
            out4[2*gi + 1] = make_float4(r.z, m.z, r.w, m.w);
        }

        // ---- Loop B: dir 0, element-wise, write odd sites only ----
        for (int e = ci; e < NDIR0; e += stride) {
            unsigned m  = (unsigned)e / 9u;    // matrix (site) index
            unsigned a  = m / 24u;  unsigned xx = m - 24u * a;
            unsigned b  = a / 24u;  unsigned yy = a - 24u * b;
            unsigned tt = b / 24u;  unsigned zz = b - 24u * tt;
            if (((xx + yy + zz + tt) & 1u) != 0u)   // odd -> copy
                out[e] = make_float2(__ldg(xre + e), __ldg(xim + e));
        }
        return;
    }

    // ---------------- COMPUTE ROLE: even dir-0 sites ----------------
    int tid = rid * TPB + threadIdx.x;          // < NEVEN

    int j    = tid % (L/2);
    int line = tid / (L/2);
    int y = line % L;
    int tz = line / L;
    int z = tz % L;
    int t = tz / L;
    int x = 2 * j + ((t + z + y) & 1);          // (t+z+y+x) even

    const float CS = 0.6366197723675814f * 0.75f / 6.0f;
    float c0s = CS * atanf(__ldg(coeff + 0));
    float c1s = CS * atanf(__ldg(coeff + 1));
    float c2s = CS * atanf(__ldg(coeff + 2));
    float c3s = CS * atanf(__ldg(coeff + 3));
    float c4s = CS * atanf(__ldg(coeff + 4));
    float c5s = CS * atanf(__ldg(coeff + 5));

    int tp = (t + 1 == L) ? 0 : t + 1;
    int zp = (z + 1 == L) ? 0 : z + 1;  int zm = (z == 0) ? L - 1 : z - 1;
    int yp = (y + 1 == L) ? 0 : y + 1;  int ym = (y == 0) ? L - 1 : y - 1;
    int xp = (x + 1 == L) ? 0 : x + 1;  int xm = (x == 0) ? L - 1 : x - 1;

    int s    = SITE(t,  z,  y,  x);
    int s_pt = SITE(tp, z,  y,  x);

    C33 f; mzero(f);
    add_staples(f, xre, xim, 1*VOL, s, SITE(t, zp, y, x), SITE(t, zm, y, x),
                s_pt, SITE(tp, zm, y, x), c0s, c1s);
    add_staples(f, xre, xim, 2*VOL, s, SITE(t, z, yp, x), SITE(t, z, ym, x),
                s_pt, SITE(tp, z, ym, x), c2s, c3s);
    add_staples(f, xre, xim, 3*VOL, s, SITE(t, z, y, xp), SITE(t, z, y, xm),
                s_pt, SITE(tp, z, y, xm), c4s, c5s);

    C33 U; loadM(U, xre, xim, s);

    // M = f @ U^dag
    C33 M; mmul_ABdag(M, f, U);

    // Q = -i * (antiherm(M) - tr/3): hermitian traceless
    C33 Q;
#pragma unroll
    for (int r = 0; r < 3; r++)
#pragma unroll
        for (int c = 0; c < 3; c++) {
            float2 m1 = M.a[r*3+c];
            float2 m2 = M.a[c*3+r];
            float zx = 0.5f * (m1.x - m2.x);     // Z real
            float zy = 0.5f * (m1.y + m2.y);     // Z imag
            Q.a[r*3+c] = make_float2(zy, -zx);   // Q = -iZ
        }
    {
        float qtx = (Q.a[0].x + Q.a[4].x + Q.a[8].x) * (1.f/3.f);
        float qty = (Q.a[0].y + Q.a[4].y + Q.a[8].y) * (1.f/3.f);
        Q.a[0].x -= qtx; Q.a[0].y -= qty;
        Q.a[4].x -= qtx; Q.a[4].y -= qty;
        Q.a[8].x -= qtx; Q.a[8].y -= qty;
    }

    // Q2 = Q @ Q
    C33 Q2; mmul(Q2, Q, Q);

    // c1 = 0.5 * Re tr(Q2);  c0 = Re det(Q)
    float c1 = 0.5f * (Q2.a[0].x + Q2.a[4].x + Q2.a[8].x);
    float c0;
    {
        float2 m00 = cmul(Q.a[4], Q.a[8]);
        float2 m01 = cmul(Q.a[5], Q.a[7]);
        float2 m10 = cmul(Q.a[3], Q.a[8]);
        float2 m11 = cmul(Q.a[5], Q.a[6]);
        float2 m20 = cmul(Q.a[3], Q.a[7]);
        float2 m21 = cmul(Q.a[4], Q.a[6]);
        float2 d0 = make_float2(m00.x - m01.x, m00.y - m01.y);
        float2 d1 = make_float2(m10.x - m11.x, m10.y - m11.y);
        float2 d2 = make_float2(m20.x - m21.x, m20.y - m21.y);
        c0 = cmul(Q.a[0], d0).x - cmul(Q.a[1], d1).x + cmul(Q.a[2], d2).x;
    }

    float2 f0, f1, f2;
    if (c1 < 1e-9f) {
        f0 = make_float2(1.f, 0.f);
        f1 = make_float2(0.f, 1.f);
        f2 = make_float2(-0.5f, 0.f);
    } else {
        bool neg = (c0 < 0.f);
        float c0a = fabsf(c0);
        float c13 = c1 * (1.f/3.f);
        float sq13 = sqrtf(c13);
        float c0max = 2.f * c13 * sq13;
        float ratio = fminf(c0a / c0max, 1.0f);
        float theta = acosf(ratio);
        float th3 = theta * (1.f/3.f);
        float s3, cth3;
        __sincosf(th3, &s3, &cth3);
        float u = sq13 * cth3;
        float w = sqrtf(c1) * s3;
        float u2 = u * u, w2 = w * w;
        float cw = __cosf(w);
        float xi0;
        if (w < 0.05f) {
            xi0 = 1.f - w2*(1.f/6.f)*(1.f - w2*(1.f/20.f)*(1.f - w2*(1.f/42.f)));
        } else {
            xi0 = __sinf(w) / w;
        }
        float su, cu;
        __sincosf(u, &su, &cu);
        float c2u = fmaf(2.f*cu, cu, -1.f);   // cos 2u
        float s2u = 2.f * su * cu;            // sin 2u

        float denom = 9.f*u2 - w2;
        float mag = 9.f*u2 + w2 + 1e-30f;
        if (fabsf(denom) < 1e-7f * mag)
            denom = copysignf(1e-7f * mag, denom == 0.f ? 1.f : denom);
        float rden = 1.f / denom;

        float a0 = 8.f*u2*cw;
        float b0 = 2.f*u*(3.f*u2 + w2)*xi0;
        float h0r = (u2 - w2)*c2u + cu*a0 + su*b0;
        float h0i = (u2 - w2)*s2u + cu*b0 - su*a0;
        float a1 = 2.f*u*cw;
        float b1 = -(3.f*u2 - w2)*xi0;
        float h1r = 2.f*u*c2u - (cu*a1 + su*b1);
        float h1i = 2.f*u*s2u - (cu*b1 - su*a1);
        float a2 = cw;
        float b2 = 3.f*u*xi0;
        float h2r = c2u - (cu*a2 + su*b2);
        float h2i = s2u - (cu*b2 - su*a2);

        f0 = make_float2(h0r*rden, h0i*rden);
        f1 = make_float2(h1r*rden, h1i*rden);
        f2 = make_float2(h2r*rden, h2i*rden);
        if (neg) {             // f_j(-c0) = (-1)^j conj(f_j)
            f0.y = -f0.y;
            f1.x = -f1.x;
            f2.y = -f2.y;
        }
    }

    // E = f0 I + f1 Q + f2 Q2
    C33 E;
#pragma unroll
    for (int k = 0; k < 9; k++) {
        float2 e = cmul(f1, Q.a[k]);
        float2 g = cmul(f2, Q2.a[k]);
        E.a[k] = make_float2(e.x + g.x, e.y + g.y);
    }
    E.a[0].x += f0.x; E.a[0].y += f0.y;
    E.a[4].x += f0.x; E.a[4].y += f0.y;
    E.a[8].x += f0.x; E.a[8].y += f0.y;

    // y[mu] = E @ U
    C33 Y; mmul(Y, E, U);

    float2* o = out + (long)s * 9;
#pragma unroll
    for (int k = 0; k < 9; k++) o[k] = Y.a[k];
}

extern "C" void kernel_launch(void* const* d_in, const int* in_sizes, int n_in,
                              void* d_out, int out_size)
{
    const float* xre   = (const float*)d_in[0];
    const float* xim   = (const float*)d_in[1];
    const float* coeff = (const float*)d_in[2];

    fused_kernel<<<NB_TOTAL, TPB>>>(xre, xim, coeff, (float2*)d_out);
}